// round 14
// baseline (speedup 1.0000x reference)
#include <cuda_runtime.h>
#include <math.h>
#include <stdint.h>

// ---------------- problem dims ----------------
#define Bn 32
#define Tn 256
#define Nn 1024
#define Mn 1024
#define G4 4096
#define BM (Bn * Mn)
#define BTN (Bn * Tn * Nn)
#define KC 128                // K elems per sub-chunk (int8 -> 128B rows)
#define NSUB 16               // 2048 / 128 (subs 0-7 = input seg, 8-15 = recurrent)
#define TILES 64              // CTAs per layer; 16 hidden units (64 gate rows) each
#define W_SUB_BYTES 16384     // 64 rows x 128 int8 x (hi+lo)
#define SUB_BYTES 24576       // W 16KB + A hi 4KB + A lo 4KB
#define GBUF_BYTES (4 * SUB_BYTES)          // 4-stage ring per group
#define SMEM_DYN (1024 + 2 * GBUF_BYTES)    // 197632
#define A_HI_OFF 16384
#define A_LO_OFF 20480
#define SWZ(o) ((o) ^ (((o) >> 3) & 0x70))

// ---------------- persistent device state (static; no allocs) ----------------
__device__ float g_h0[2][BM];
__device__ float g_h1[2][BM];
__device__ float g_c0[BM];
__device__ float g_c1[BM];
__device__ char  g_h0q[2][2][BM];           // [dbuf][hi/lo] int8 h (layer0)
__device__ char  g_h1q[2][2][BM];
__device__ char  g_xq[2][BTN];              // [hi/lo] int8 x
__device__ unsigned char g_Wpk[(size_t)2 * TILES * NSUB * W_SUB_BYTES];  // 32MB
__device__ float g_swr[2 * G4];             // per-(layer,row) weight scale
__device__ int   g_sa_bits;                 // float bits of max|x| (atomicMax)

__device__ __forceinline__ float sigmoidf_(float z) { return 1.0f / (1.0f + expf(-z)); }

__device__ __forceinline__ uint32_t smem_u32(const void* p) {
    uint32_t a;
    asm("{ .reg .u64 t; cvta.to.shared.u64 t, %1; cvt.u32.u64 %0, t; }" : "=r"(a) : "l"(p));
    return a;
}

// quantize v -> (hi, lo) int8 pair: v = s/127 * (hi + lo/256), s given
__device__ __forceinline__ void quant2(float v, float inv_s127, char& qh, char& ql) {
    float u = v * inv_s127;                       // in [-127, 127]
    int hi = __float2int_rn(u);
    float res = u - (float)hi;                    // [-0.5, 0.5]
    int lo = __float2int_rn(res * 256.0f);
    lo = max(-128, min(127, lo));
    qh = (char)hi; ql = (char)lo;
}

#define LDSM4(R, A)                                                                  \
    asm volatile("ldmatrix.sync.aligned.m8n8.x4.shared.b16 {%0,%1,%2,%3}, [%4];"     \
                 : "=r"((R)[0]), "=r"((R)[1]), "=r"((R)[2]), "=r"((R)[3]) : "r"(A))

#define MMAS8(D, Av, B0, B1)                                                         \
    asm volatile("mma.sync.aligned.m16n8k32.row.col.s32.s8.s8.s32 "                  \
                 "{%0,%1,%2,%3},{%4,%5,%6,%7},{%8,%9},{%0,%1,%2,%3};"                \
                 : "+r"((D)[0]), "+r"((D)[1]), "+r"((D)[2]), "+r"((D)[3])            \
                 : "r"((Av)[0]), "r"((Av)[1]), "r"((Av)[2]), "r"((Av)[3]),           \
                   "r"(B0), "r"(B1))

#define CPA16(dst, src) \
    asm volatile("cp.async.cg.shared.global [%0], [%1], 16;" :: "r"(dst), "l"(src))
#define CPCOMMIT() asm volatile("cp.async.commit_group;" ::: "memory")
#define GBAR(id) asm volatile("bar.sync %0, 256;" :: "r"(id) : "memory")

// ---------------- scale kernels ----------------
__global__ void zero_sa_kernel() { g_sa_bits = 0; }

__global__ void absmax_x_kernel(const float* __restrict__ x) {
    __shared__ float red[256];
    float m = 0.0f;
    for (size_t i = blockIdx.x * blockDim.x + threadIdx.x; i < BTN;
         i += (size_t)gridDim.x * blockDim.x)
        m = fmaxf(m, fabsf(x[i]));
    red[threadIdx.x] = m;
    __syncthreads();
    for (int s = 128; s > 0; s >>= 1) {
        if (threadIdx.x < s) red[threadIdx.x] = fmaxf(red[threadIdx.x], red[threadIdx.x + s]);
        __syncthreads();
    }
    if (threadIdx.x == 0) atomicMax(&g_sa_bits, __float_as_int(fmaxf(red[0], 1e-8f)));
}

// per-(layer,row) weight absmax over full K=2048 (Wih row + Whh row)
__global__ void w_rowmax_kernel(const float* __restrict__ Wih, const float* __restrict__ Whh) {
    __shared__ float red[256];
    int l = blockIdx.x >> 12;
    int R = blockIdx.x & 4095;
    const float* a = Wih + ((size_t)l * G4 + R) * 1024;
    const float* b = Whh + ((size_t)l * G4 + R) * 1024;
    float m = 0.0f;
    for (int k = threadIdx.x; k < 1024; k += 256)
        m = fmaxf(m, fmaxf(fabsf(a[k]), fabsf(b[k])));
    red[threadIdx.x] = m;
    __syncthreads();
    for (int s = 128; s > 0; s >>= 1) {
        if (threadIdx.x < s) red[threadIdx.x] = fmaxf(red[threadIdx.x], red[threadIdx.x + s]);
        __syncthreads();
    }
    if (threadIdx.x == 0) g_swr[l * G4 + R] = fmaxf(red[0], 1e-8f);
}

// ---------------- init: state copy + h quantization (needs g_sa) ----------------
__global__ void lstm_init_kernel(const float* __restrict__ h, const float* __restrict__ c) {
    int i = blockIdx.x * blockDim.x + threadIdx.x;
    if (i >= 2 * BM) return;
    float sa = __int_as_float(g_sa_bits);
    float inv = 127.0f / sa;
    float hv = h[i];
    char qh, ql;
    quant2(hv, inv, qh, ql);
    if (i < BM) {
        g_h0[0][i] = hv;  g_c0[i] = c[i];
        g_h0q[0][0][i] = qh;  g_h0q[0][1][i] = ql;
    } else {
        int j = i - BM;
        g_h1[0][j] = hv;  g_c1[j] = c[i];
        g_h1q[0][0][j] = qh;  g_h1q[0][1][j] = ql;
    }
}

// ---------------- final ----------------
__global__ void lstm_final_kernel(float* __restrict__ out) {
    int i = blockIdx.x * blockDim.x + threadIdx.x;
    if (i >= 2 * BM) return;
    const int base = Bn * Tn * Mn;
    float hv, cv;
    if (i < BM) { hv = g_h0[0][i];      cv = g_c0[i]; }
    else        { hv = g_h1[0][i - BM]; cv = g_c1[i - BM]; }
    out[base + i] = hv;
    out[base + 2 * BM + i] = cv;
}

// ---------------- pack x -> int8 hi/lo ----------------
__global__ void pack_x_kernel(const float* __restrict__ x) {
    int idx = blockIdx.x * blockDim.x + threadIdx.x;   // one per 16 elems (524288)
    float inv = 127.0f / __int_as_float(g_sa_bits);
    const float* src = x + (size_t)idx * 16;
    char qh[16], ql[16];
#pragma unroll
    for (int e = 0; e < 16; e++) quant2(src[e], inv, qh[e], ql[e]);
    *reinterpret_cast<int4*>(g_xq[0] + (size_t)idx * 16) = *reinterpret_cast<int4*>(qh);
    *reinterpret_cast<int4*>(g_xq[1] + (size_t)idx * 16) = *reinterpret_cast<int4*>(ql);
}

// ---------------- pack weights -> int8 hi/lo, tile/sub-major, pre-swizzled ----------------
// one thread per 16-elem granule: idx = [l][tile][sub][r][kq], 1,048,576 total
__global__ void pack_w_kernel(const float* __restrict__ Wih, const float* __restrict__ Whh) {
    int idx = blockIdx.x * blockDim.x + threadIdx.x;
    int kq   = idx & 7;
    int r    = (idx >> 3) & 63;
    int sub  = (idx >> 9) & 15;
    int tile = (idx >> 13) & 63;
    int l    = (idx >> 19) & 1;
    int gate = r >> 4, ul = r & 15;
    int R = gate * 1024 + tile * 16 + ul;
    int seg = sub >> 3, k0 = (sub & 7) * KC + kq * 16;
    const float* W = (seg ? Whh : Wih) + ((size_t)l * G4 + R) * 1024 + k0;
    float inv = 127.0f / g_swr[l * G4 + R];
    char qh[16], ql[16];
#pragma unroll
    for (int e = 0; e < 16; e++) quant2(W[e], inv, qh[e], ql[e]);
    size_t base = (size_t)((l * TILES + tile) * NSUB + sub) * W_SUB_BYTES;
    uint32_t sw = SWZ((uint32_t)(r * 128 + kq * 16));
    *reinterpret_cast<int4*>(g_Wpk + base + sw)        = *reinterpret_cast<int4*>(qh);
    *reinterpret_cast<int4*>(g_Wpk + base + 8192 + sw) = *reinterpret_cast<int4*>(ql);
}

// ---------------- step kernel: skewed 2-layer, dual 8-warp groups, int8 4-term ----------------
// grid = 128: blocks 0..63 layer0 step t, 64..127 layer1 step t-1.
// CTA = 16 units (64 gate rows) x 32 batch. Group g (256 thr) handles subs 2i+g,
// 4-stage ring, one group barrier per sub.
__global__ __launch_bounds__(512, 1)
void lstm_step_mma(int t,
                   const float* __restrict__ bih, const float* __restrict__ bhh,
                   float* __restrict__ out) {
    const int layer = blockIdx.x >> 6;
    const int tile  = blockIdx.x & 63;
    if (layer == 0 && t >= Tn) return;
    if (layer == 1 && t == 0)  return;
    const int s = layer ? (t - 1) : t;
    const int U = tile * 16;
    const int tid = threadIdx.x;
    const int lane = tid & 31;
    const int grp  = tid >> 8;
    const int gtid = tid & 255;
    const int gwid = (tid >> 5) & 7;

    // int8 activation sources + state targets
    const char *qhi0, *qlo0, *qhi1, *qlo1;
    size_t st0;
    const size_t st1 = 1024;
    float* hout; float* cst;
    char *hq_hi, *hq_lo;
    if (layer == 0) {
        qhi0 = g_xq[0] + (size_t)t * Nn;  qlo0 = g_xq[1] + (size_t)t * Nn;
        st0 = (size_t)Tn * Nn;
        qhi1 = g_h0q[t & 1][0];  qlo1 = g_h0q[t & 1][1];
        hout = g_h0[(t & 1) ^ 1]; cst = g_c0;
        hq_hi = g_h0q[(t & 1) ^ 1][0]; hq_lo = g_h0q[(t & 1) ^ 1][1];
    } else {
        qhi0 = g_h0q[t & 1][0];  qlo0 = g_h0q[t & 1][1];
        st0 = st1;
        qhi1 = g_h1q[s & 1][0];  qlo1 = g_h1q[s & 1][1];
        hout = g_h1[(s & 1) ^ 1]; cst = g_c1;
        hq_hi = g_h1q[(s & 1) ^ 1][0]; hq_lo = g_h1q[(s & 1) ^ 1][1];
    }

    extern __shared__ __align__(16) char smraw[];
    const uint32_t sraw = smem_u32(smraw);
    const uint32_t sb   = (sraw + 1023) & ~1023u;
    char* sgen = smraw + (sb - sraw);
    const unsigned char* wsrc = g_Wpk + (size_t)((layer * TILES + tile) * NSUB) * W_SUB_BYTES;

    // warp roles within group: 4 row-groups x 2 batch-halves
    const int rg = gwid >> 1, nh = gwid & 1;
    const uint32_t woff0 = (uint32_t)((rg * 16 + (lane & 15)) * 128 + (lane >> 4) * 16);
    const uint32_t aoff0 = (uint32_t)((nh * 16 + ((lane >> 4) << 3) + (lane & 7)) * 128
                                      + ((lane >> 3) & 1) * 16);

    int Dm[2][4], Dc[2][4], Dll[2][4];
#pragma unroll
    for (int i = 0; i < 2; i++)
#pragma unroll
        for (int j = 0; j < 4; j++) { Dm[i][j] = 0; Dc[i][j] = 0; Dll[i][j] = 0; }

    // per-thread fill constants (group-local)
    const int ar_  = gtid >> 3;                // batch row 0..31
    const int akq_ = gtid & 7;                 // 16B col within 128B row
    const uint32_t a_sw = SWZ((uint32_t)(ar_ * 128 + akq_ * 16));
    const uint32_t gbase = sb + (uint32_t)grp * GBUF_BYTES;

#define FILL(buf_, sub_)                                                             \
    do {                                                                             \
        uint32_t d_ = gbase + (buf_) * SUB_BYTES;                                    \
        const unsigned char* ws_ = wsrc + (size_t)(sub_) * W_SUB_BYTES;              \
        _Pragma("unroll")                                                            \
        for (int i_ = 0; i_ < 4; i_++)                                               \
            CPA16(d_ + i_ * 4096 + gtid * 16, ws_ + i_ * 4096 + gtid * 16);          \
        int seg_ = (sub_) >> 3;                                                      \
        size_t ko_ = (size_t)((sub_) & 7) * KC + akq_ * 16;                          \
        size_t as_ = seg_ ? st1 : st0;                                               \
        const char* sh_ = (seg_ ? qhi1 : qhi0) + (size_t)ar_ * as_ + ko_;            \
        const char* sl_ = (seg_ ? qlo1 : qlo0) + (size_t)ar_ * as_ + ko_;            \
        CPA16(d_ + A_HI_OFF + a_sw, sh_);                                            \
        CPA16(d_ + A_LO_OFF + a_sw, sl_);                                            \
    } while (0)

    // ---- prologue: prefetch 3 subs ----
    FILL(0, grp);     CPCOMMIT();
    FILL(1, grp + 2); CPCOMMIT();
    FILL(2, grp + 4); CPCOMMIT();

    const int barid = grp + 1;

    // ---- per-group pipeline: 8 subs, one group barrier each ----
    for (int i = 0; i < 8; i++) {
        if (i <= 5)      asm volatile("cp.async.wait_group 2;" ::: "memory");
        else if (i == 6) asm volatile("cp.async.wait_group 1;" ::: "memory");
        else             asm volatile("cp.async.wait_group 0;" ::: "memory");
        GBAR(barid);     // sub i landed; whole group done with buffer (i-1)&3

        if (i + 3 < 8) { FILL((i + 3) & 3, grp + 2 * (i + 3)); CPCOMMIT(); }

        const uint32_t wb = gbase + (uint32_t)(i & 3) * SUB_BYTES;
#pragma unroll
        for (int ks = 0; ks < 4; ks++) {       // 4 x k32 over 128 int8
            uint32_t wo = SWZ(woff0 + ks * 32);
            uint32_t ao = SWZ(aoff0 + ks * 32);
            uint32_t whi[4], wlo[4], ahi[4], alo[4];
            LDSM4(whi, wb + wo);
            LDSM4(wlo, wb + 8192 + wo);
            LDSM4(ahi, wb + A_HI_OFF + ao);
            LDSM4(alo, wb + A_LO_OFF + ao);
#pragma unroll
            for (int nt = 0; nt < 2; nt++) {
                MMAS8(Dm[nt],  whi, ahi[2 * nt], ahi[2 * nt + 1]);   // hi.hi
                MMAS8(Dc[nt],  wlo, ahi[2 * nt], ahi[2 * nt + 1]);   // lo.hi   (1/256)
                MMAS8(Dc[nt],  whi, alo[2 * nt], alo[2 * nt + 1]);   // hi.lo   (1/256)
                MMAS8(Dll[nt], wlo, alo[2 * nt], alo[2 * nt + 1]);   // lo.lo (1/65536)
            }
        }
    }
#undef FILL

    // ---- epilogue: scale + combine -> group z plane (aliases group buffer 0) ----
    const float sa  = __int_as_float(g_sa_bits);
    const float sac = sa / 16129.0f;                   // sa / (127*127)
    {
        float* zp = (float*)(sgen + (size_t)grp * GBUF_BYTES);
        const int r0 = rg * 16 + (lane >> 2);          // CTA rows r0, r0+8 (same gate)
        const int Rg = (r0 >> 4) * 1024 + U + (r0 & 15);
        const float sc0 = g_swr[layer * G4 + Rg] * sac;
        const float sc8 = g_swr[layer * G4 + Rg + 8] * sac;
        const int c0 = nh * 16 + (lane & 3) * 2;
        const float C1 = 0.00390625f, C2 = 1.52587890625e-05f;
#pragma unroll
        for (int nt = 0; nt < 2; nt++) {
            float d0 = ((float)Dm[nt][0] + (float)Dc[nt][0] * C1 + (float)Dll[nt][0] * C2) * sc0;
            float d1 = ((float)Dm[nt][1] + (float)Dc[nt][1] * C1 + (float)Dll[nt][1] * C2) * sc0;
            float d2 = ((float)Dm[nt][2] + (float)Dc[nt][2] * C1 + (float)Dll[nt][2] * C2) * sc8;
            float d3 = ((float)Dm[nt][3] + (float)Dc[nt][3] * C1 + (float)Dll[nt][3] * C2) * sc8;
            int cc = c0 + nt * 8;
            zp[r0 * 33 + cc]           = d0;
            zp[r0 * 33 + cc + 1]       = d1;
            zp[(r0 + 8) * 33 + cc]     = d2;
            zp[(r0 + 8) * 33 + cc + 1] = d3;
        }
    }
    __syncthreads();   // both groups' planes complete

    // pointwise: 512 threads -> one (unit, batch) each; sum the two group planes
    const float* z0 = (const float*)sgen;
    const float* z1 = (const float*)(sgen + GBUF_BYTES);
    const int ul = tid & 15;
    const int b  = tid >> 4;                  // 0..31
    float zg4[4];
#pragma unroll
    for (int g = 0; g < 4; g++) {
        int j = layer * G4 + g * 1024 + U + ul;
        int row = g * 16 + ul;
        zg4[g] = z0[row * 33 + b] + z1[row * 33 + b] + bih[j] + bhh[j];
    }
    {
        int idx = b * Mn + U + ul;
        float ig = sigmoidf_(zg4[0]), fg = sigmoidf_(zg4[1]), og = sigmoidf_(zg4[3]);
        float gg = tanhf(zg4[2]);
        float cn = fmaf(fg, cst[idx], ig * gg);
        cst[idx] = cn;
        float hh = og * tanhf(cn);
        hout[idx] = hh;
        char qh, ql;
        quant2(hh, 127.0f / sa, qh, ql);
        hq_hi[idx] = qh;  hq_lo[idx] = ql;
        if (layer == 1)
            out[((size_t)b * Tn + s) * Mn + U + ul] = hh;
    }
}

// ---------------- launch ----------------
extern "C" void kernel_launch(void* const* d_in, const int* in_sizes, int n_in,
                              void* d_out, int out_size) {
    (void)in_sizes; (void)n_in; (void)out_size;
    const float* x   = (const float*)d_in[0];
    const float* h   = (const float*)d_in[1];
    const float* c   = (const float*)d_in[2];
    const float* Wih = (const float*)d_in[3];
    const float* Whh = (const float*)d_in[4];
    const float* bih = (const float*)d_in[5];
    const float* bhh = (const float*)d_in[6];
    float* out = (float*)d_out;

    static int smem_set = 0;
    if (!smem_set) {
        cudaFuncSetAttribute(lstm_step_mma,
                             cudaFuncAttributeMaxDynamicSharedMemorySize, SMEM_DYN);
        smem_set = 1;
    }

    zero_sa_kernel<<<1, 1>>>();
    absmax_x_kernel<<<1024, 256>>>(x);
    lstm_init_kernel<<<(2 * BM + 255) / 256, 256>>>(h, c);
    w_rowmax_kernel<<<2 * G4, 256>>>(Wih, Whh);
    pack_w_kernel<<<4096, 256>>>(Wih, Whh);
    pack_x_kernel<<<2048, 256>>>(x);

    for (int t = 0; t <= Tn; ++t)
        lstm_step_mma<<<2 * TILES, 512, SMEM_DYN>>>(t, bih, bhh, out);

    lstm_final_kernel<<<(2 * BM + 255) / 256, 256>>>(out);
}

// round 17
// speedup vs baseline: 3.3203x; 3.3203x over previous
#include <cuda_runtime.h>
#include <cuda_fp16.h>
#include <math.h>
#include <stdint.h>

// ---------------- problem dims ----------------
#define Bn 32
#define Tn 256
#define Nn 1024
#define Mn 1024
#define G4 4096
#define BM (Bn * Mn)
#define BTN (Bn * Tn * Nn)
#define KC 64                 // K elems per sub-chunk (fp16 -> 128B rows)
#define NSUB 32               // 2048/64: subs 0-15 input seg, 16-31 recurrent
#define TILES 64              // CTAs per layer; 16 hidden units (64 gate rows) each
#define W_SUB_BYTES 8192      // 64 rows x 64 fp16 (single precision level)
#define SUB_BYTES 16384       // W 8KB + A hi 4KB + A lo 4KB
#define NSTG 6                // ring stages per group
#define GBUF_BYTES (NSTG * SUB_BYTES)       // 98304
#define SMEM_DYN (1024 + 2 * GBUF_BYTES)    // 197632
#define A_HI_OFF 8192
#define A_LO_OFF 12288
#define SWZ(o) ((o) ^ (((o) >> 3) & 0x70))

// ---------------- persistent device state (static; no allocs) ----------------
__device__ float g_h0[2][BM];
__device__ float g_h1[2][BM];
__device__ float g_c0[BM];
__device__ float g_c1[BM];
__device__ __half g_h0f[2][2][BM];          // [dbuf][hi/lo] fp16 h (layer0)
__device__ __half g_h1f[2][2][BM];
__device__ __half g_xf[2][BTN];             // [hi/lo] fp16 x
__device__ unsigned char g_Wpk[(size_t)2 * TILES * NSUB * W_SUB_BYTES];  // 32MB

__device__ __forceinline__ float sigmoidf_(float z) { return 1.0f / (1.0f + expf(-z)); }

__device__ __forceinline__ uint32_t smem_u32(const void* p) {
    uint32_t a;
    asm("{ .reg .u64 t; cvta.to.shared.u64 t, %1; cvt.u32.u64 %0, t; }" : "=r"(a) : "l"(p));
    return a;
}

// fp16 hi/lo split: v = hi + lo exactly to ~2^-22 relative
__device__ __forceinline__ void splith(float v, __half& hi, __half& lo) {
    hi = __float2half(v);
    lo = __float2half(v - __half2float(hi));
}

#define LDSM4(R, A)                                                                  \
    asm volatile("ldmatrix.sync.aligned.m8n8.x4.shared.b16 {%0,%1,%2,%3}, [%4];"     \
                 : "=r"((R)[0]), "=r"((R)[1]), "=r"((R)[2]), "=r"((R)[3]) : "r"(A))

#define MMAH(D, Av, B0, B1)                                                          \
    asm volatile("mma.sync.aligned.m16n8k16.row.col.f32.f16.f16.f32 "                \
                 "{%0,%1,%2,%3},{%4,%5,%6,%7},{%8,%9},{%0,%1,%2,%3};"                \
                 : "+f"((D)[0]), "+f"((D)[1]), "+f"((D)[2]), "+f"((D)[3])            \
                 : "r"((Av)[0]), "r"((Av)[1]), "r"((Av)[2]), "r"((Av)[3]),           \
                   "r"(B0), "r"(B1))

#define CPA16(dst, src) \
    asm volatile("cp.async.cg.shared.global [%0], [%1], 16;" :: "r"(dst), "l"(src))
#define CPCOMMIT() asm volatile("cp.async.commit_group;" ::: "memory")
#define GBAR(id) asm volatile("bar.sync %0, 256;" :: "r"(id) : "memory")

// ---------------- init ----------------
__global__ void lstm_init_kernel(const float* __restrict__ h, const float* __restrict__ c) {
    int i = blockIdx.x * blockDim.x + threadIdx.x;
    if (i >= 2 * BM) return;
    float hv = h[i];
    __half hh, hl;
    splith(hv, hh, hl);
    if (i < BM) {
        g_h0[0][i] = hv;  g_c0[i] = c[i];
        g_h0f[0][0][i] = hh;  g_h0f[0][1][i] = hl;
    } else {
        int j = i - BM;
        g_h1[0][j] = hv;  g_c1[j] = c[i];
        g_h1f[0][0][j] = hh;  g_h1f[0][1][j] = hl;
    }
}

// ---------------- final ----------------
__global__ void lstm_final_kernel(float* __restrict__ out) {
    int i = blockIdx.x * blockDim.x + threadIdx.x;
    if (i >= 2 * BM) return;
    const int base = Bn * Tn * Mn;
    float hv, cv;
    if (i < BM) { hv = g_h0[0][i];      cv = g_c0[i]; }
    else        { hv = g_h1[0][i - BM]; cv = g_c1[i - BM]; }
    out[base + i] = hv;
    out[base + 2 * BM + i] = cv;
}

// ---------------- pack x -> fp16 hi/lo (one thread per 8 elems) ----------------
__global__ void pack_x_kernel(const float* __restrict__ x) {
    int idx = blockIdx.x * blockDim.x + threadIdx.x;   // BTN/8 = 1,048,576
    const float* src = x + (size_t)idx * 8;
    __half qh[8], ql[8];
#pragma unroll
    for (int e = 0; e < 8; e++) splith(src[e], qh[e], ql[e]);
    *reinterpret_cast<int4*>((char*)g_xf[0] + (size_t)idx * 16) = *reinterpret_cast<int4*>(qh);
    *reinterpret_cast<int4*>((char*)g_xf[1] + (size_t)idx * 16) = *reinterpret_cast<int4*>(ql);
}

// ---------------- pack weights -> fp16 single, tile/sub-major, pre-swizzled ----------------
// one thread per 16B granule (8 k elems): idx = [l][tile][sub][r][kq], 2,097,152 total
__global__ void pack_w_kernel(const float* __restrict__ Wih, const float* __restrict__ Whh) {
    int idx = blockIdx.x * blockDim.x + threadIdx.x;
    int kq   = idx & 7;
    int r    = (idx >> 3) & 63;
    int sub  = (idx >> 9) & 31;
    int tile = (idx >> 14) & 63;
    int l    = (idx >> 20) & 1;
    int gate = r >> 4, ul = r & 15;
    int R = gate * 1024 + tile * 16 + ul;
    int seg = sub >> 4, k0 = (sub & 15) * KC + kq * 8;
    const float* W = (seg ? Whh : Wih) + ((size_t)l * G4 + R) * 1024 + k0;
    __half q[8];
#pragma unroll
    for (int e = 0; e < 8; e++) q[e] = __float2half(W[e]);
    size_t base = (size_t)((l * TILES + tile) * NSUB + sub) * W_SUB_BYTES;
    uint32_t sw = SWZ((uint32_t)(r * 128 + kq * 16));
    *reinterpret_cast<int4*>(g_Wpk + base + sw) = *reinterpret_cast<int4*>(q);
}

// ---------------- step kernel: skewed 2-layer, dual 8-warp groups, fp16 2-term ----------------
// grid = 128: blocks 0..63 layer0 step t, 64..127 layer1 step t-1.
// CTA = 16 units (64 gate rows) x 32 batch. Group g (256 thr) handles subs 2i+g,
// 6-stage ring, prefetch 5 ahead, ONE group barrier per sub.
__global__ __launch_bounds__(512, 1)
void lstm_step_mma(int t,
                   const float* __restrict__ bih, const float* __restrict__ bhh,
                   float* __restrict__ out) {
    const int layer = blockIdx.x >> 6;
    const int tile  = blockIdx.x & 63;
    if (layer == 0 && t >= Tn) return;
    if (layer == 1 && t == 0)  return;
    const int s = layer ? (t - 1) : t;
    const int U = tile * 16;
    const int tid = threadIdx.x;
    const int lane = tid & 31;
    const int grp  = tid >> 8;
    const int gtid = tid & 255;
    const int gwid = (tid >> 5) & 7;

    // fp16 activation sources (byte pointers) + state targets
    const char *hi0, *lo0, *hi1, *lo1;
    size_t st0;                                // byte stride between batch rows
    const size_t st1 = (size_t)Mn * 2;
    float* hout; float* cst;
    __half *hq_hi, *hq_lo;
    if (layer == 0) {
        hi0 = (const char*)g_xf[0] + (size_t)t * Nn * 2;
        lo0 = (const char*)g_xf[1] + (size_t)t * Nn * 2;
        st0 = (size_t)Tn * Nn * 2;
        hi1 = (const char*)g_h0f[t & 1][0];  lo1 = (const char*)g_h0f[t & 1][1];
        hout = g_h0[(t & 1) ^ 1]; cst = g_c0;
        hq_hi = g_h0f[(t & 1) ^ 1][0]; hq_lo = g_h0f[(t & 1) ^ 1][1];
    } else {
        hi0 = (const char*)g_h0f[t & 1][0];  lo0 = (const char*)g_h0f[t & 1][1];
        st0 = st1;
        hi1 = (const char*)g_h1f[s & 1][0];  lo1 = (const char*)g_h1f[s & 1][1];
        hout = g_h1[(s & 1) ^ 1]; cst = g_c1;
        hq_hi = g_h1f[(s & 1) ^ 1][0]; hq_lo = g_h1f[(s & 1) ^ 1][1];
    }

    extern __shared__ __align__(16) char smraw[];
    const uint32_t sraw = smem_u32(smraw);
    const uint32_t sb   = (sraw + 1023) & ~1023u;
    char* sgen = smraw + (sb - sraw);
    const unsigned char* wsrc = g_Wpk + (size_t)((layer * TILES + tile) * NSUB) * W_SUB_BYTES;

    // warp roles within group: 4 row-groups x 2 batch-halves
    const int rg = gwid >> 1, nh = gwid & 1;
    const uint32_t woff0 = (uint32_t)((rg * 16 + (lane & 15)) * 128 + (lane >> 4) * 16);
    const uint32_t aoff0 = (uint32_t)((nh * 16 + ((lane >> 4) << 3) + (lane & 7)) * 128
                                      + ((lane >> 3) & 1) * 16);

    float acc[4][4];                            // [term*2+nt][frag]
#pragma unroll
    for (int i = 0; i < 4; i++)
#pragma unroll
        for (int j = 0; j < 4; j++) acc[i][j] = 0.0f;

    // per-thread fill constants (group-local 256 threads)
    const int ar_  = gtid >> 3;                // batch row 0..31
    const int akq_ = gtid & 7;                 // 16B col within 128B row
    const uint32_t a_sw = SWZ((uint32_t)(ar_ * 128 + akq_ * 16));
    const uint32_t gbase = sb + (uint32_t)grp * GBUF_BYTES;

    // FILL local sub j (global sub = 2*j + grp) into ring buffer (j % 6)
#define FILL(buf_, j_)                                                               \
    do {                                                                             \
        int sub_ = 2 * (j_) + grp;                                                   \
        uint32_t d_ = gbase + (buf_) * SUB_BYTES;                                    \
        const unsigned char* ws_ = wsrc + (size_t)sub_ * W_SUB_BYTES;                \
        CPA16(d_ + gtid * 16,        ws_ + gtid * 16);                               \
        CPA16(d_ + 4096 + gtid * 16, ws_ + 4096 + gtid * 16);                        \
        int seg_ = sub_ >> 4;                                                        \
        size_t ko_ = (size_t)(sub_ & 15) * 128 + akq_ * 16;                          \
        size_t as_ = seg_ ? st1 : st0;                                               \
        const char* sh_ = (seg_ ? hi1 : hi0) + (size_t)ar_ * as_ + ko_;              \
        const char* sl_ = (seg_ ? lo1 : lo0) + (size_t)ar_ * as_ + ko_;              \
        CPA16(d_ + A_HI_OFF + a_sw, sh_);                                            \
        CPA16(d_ + A_LO_OFF + a_sw, sl_);                                            \
    } while (0)

    // ---- prologue: prefetch 5 subs deep ----
    FILL(0, 0); CPCOMMIT();
    FILL(1, 1); CPCOMMIT();
    FILL(2, 2); CPCOMMIT();
    FILL(3, 3); CPCOMMIT();
    FILL(4, 4); CPCOMMIT();

    const int barid = grp + 1;

    // ---- per-group pipeline: 16 local subs, one group barrier per sub ----
#pragma unroll
    for (int i = 0; i < 16; i++) {
        if (i <= 11)      asm volatile("cp.async.wait_group 4;" ::: "memory");
        else if (i == 12) asm volatile("cp.async.wait_group 3;" ::: "memory");
        else if (i == 13) asm volatile("cp.async.wait_group 2;" ::: "memory");
        else if (i == 14) asm volatile("cp.async.wait_group 1;" ::: "memory");
        else              asm volatile("cp.async.wait_group 0;" ::: "memory");
        GBAR(barid);   // sub i landed for whole group; group done computing sub i-1

        if (i + 5 < 16) { FILL((i + 5) % NSTG, i + 5); CPCOMMIT(); }

        const uint32_t wb = gbase + (uint32_t)(i % NSTG) * SUB_BYTES;
#pragma unroll
        for (int ks = 0; ks < 4; ks++) {
            uint32_t wo = SWZ(woff0 + ks * 32);
            uint32_t ao = SWZ(aoff0 + ks * 32);
            uint32_t w4[4], ah[4], al[4];
            LDSM4(w4, wb + wo);
            LDSM4(ah, wb + A_HI_OFF + ao);
            LDSM4(al, wb + A_LO_OFF + ao);
            MMAH(acc[0], w4, ah[0], ah[1]);    // nt0: W.Ahi
            MMAH(acc[1], w4, ah[2], ah[3]);    // nt1: W.Ahi
            MMAH(acc[2], w4, al[0], al[1]);    // nt0: W.Alo
            MMAH(acc[3], w4, al[2], al[3]);    // nt1: W.Alo
        }
    }
#undef FILL

    // ---- epilogue: combine terms -> group z plane (aliases group buffer 0) ----
    {
        float* zp = (float*)(sgen + (size_t)grp * GBUF_BYTES);
        const int r0 = rg * 16 + (lane >> 2);
        const int c0 = nh * 16 + (lane & 3) * 2;
#pragma unroll
        for (int nt = 0; nt < 2; nt++) {
            float d0 = acc[nt][0] + acc[nt + 2][0];
            float d1 = acc[nt][1] + acc[nt + 2][1];
            float d2 = acc[nt][2] + acc[nt + 2][2];
            float d3 = acc[nt][3] + acc[nt + 2][3];
            int cc = c0 + nt * 8;
            zp[r0 * 33 + cc]           = d0;
            zp[r0 * 33 + cc + 1]       = d1;
            zp[(r0 + 8) * 33 + cc]     = d2;
            zp[(r0 + 8) * 33 + cc + 1] = d3;
        }
    }
    __syncthreads();   // both groups' planes complete

    // pointwise: 512 threads -> one (unit, batch) each; sum the two group planes
    const float* z0 = (const float*)sgen;
    const float* z1 = (const float*)(sgen + GBUF_BYTES);
    const int ul = tid & 15;
    const int b  = tid >> 4;                  // 0..31
    float zg4[4];
#pragma unroll
    for (int g = 0; g < 4; g++) {
        int j = layer * G4 + g * 1024 + U + ul;
        int row = g * 16 + ul;
        zg4[g] = z0[row * 33 + b] + z1[row * 33 + b] + bih[j] + bhh[j];
    }
    {
        int idx = b * Mn + U + ul;
        float ig = sigmoidf_(zg4[0]), fg = sigmoidf_(zg4[1]), og = sigmoidf_(zg4[3]);
        float gg = tanhf(zg4[2]);
        float cn = fmaf(fg, cst[idx], ig * gg);
        cst[idx] = cn;
        float hh = og * tanhf(cn);
        hout[idx] = hh;
        __half qh, ql;
        splith(hh, qh, ql);
        hq_hi[idx] = qh;  hq_lo[idx] = ql;
        if (layer == 1)
            out[((size_t)b * Tn + s) * Mn + U + ul] = hh;
    }
}

// ---------------- launch ----------------
extern "C" void kernel_launch(void* const* d_in, const int* in_sizes, int n_in,
                              void* d_out, int out_size) {
    (void)in_sizes; (void)n_in; (void)out_size;
    const float* x   = (const float*)d_in[0];
    const float* h   = (const float*)d_in[1];
    const float* c   = (const float*)d_in[2];
    const float* Wih = (const float*)d_in[3];
    const float* Whh = (const float*)d_in[4];
    const float* bih = (const float*)d_in[5];
    const float* bhh = (const float*)d_in[6];
    float* out = (float*)d_out;

    static int smem_set = 0;
    if (!smem_set) {
        cudaFuncSetAttribute(lstm_step_mma,
                             cudaFuncAttributeMaxDynamicSharedMemorySize, SMEM_DYN);
        smem_set = 1;
    }

    lstm_init_kernel<<<(2 * BM + 255) / 256, 256>>>(h, c);
    pack_x_kernel<<<BTN / 8 / 256, 256>>>(x);
    pack_w_kernel<<<(2 * TILES * NSUB * 64 * 8) / 256, 256>>>(Wih, Whh);

    for (int t = 0; t <= Tn; ++t)
        lstm_step_mma<<<2 * TILES, 512, SMEM_DYN>>>(t, bih, bhh, out);

    lstm_final_kernel<<<(2 * BM + 255) / 256, 256>>>(out);
}